// round 9
// baseline (speedup 1.0000x reference)
#include <cuda_runtime.h>
#include <cuda_fp16.h>

#define NB_ 16384
#define SCALE_ 0.17677669529663687f  // 1/sqrt(32)

typedef unsigned u32;

// ---- interleaved weight fragment buffers: uint4 = {b0_hi, b1_hi, b0_lo, b1_lo} ----
__device__ __align__(16) uint4 g_wqkv_i[48 * 8 * 32];  // 196608 B
__device__ __align__(16) uint4 g_wo_i[16 * 8 * 32];    //  65536 B

__device__ __forceinline__ void split_pair(float a, float b, u32& hi, u32& lo) {
    __half ha = __float2half_rn(a), hb = __float2half_rn(b);
    __half2 h2 = __halves2half2(ha, hb);
    hi = *(u32*)&h2;
    __half2 l2 = __floats2half2_rn(a - __half2float(ha), b - __half2float(hb));
    lo = *(u32*)&l2;
}
__device__ __forceinline__ void split_one(float v, __half* ph, __half* pl) {
    __half h = __float2half_rn(v);
    *ph = h;
    *pl = __float2half_rn(v - __half2float(h));
}
__device__ __forceinline__ u32 smem_u32(const void* p) {
    u32 a;
    asm("{ .reg .u64 t; cvta.to.shared.u64 t, %1; cvt.u32.u64 %0, t; }" : "=r"(a) : "l"(p));
    return a;
}

__device__ __forceinline__ void mma16816(float* d, const u32* a, const u32* b) {
    asm volatile(
        "mma.sync.aligned.m16n8k16.row.col.f32.f16.f16.f32 "
        "{%0,%1,%2,%3}, {%4,%5,%6,%7}, {%8,%9}, {%0,%1,%2,%3};\n"
        : "+f"(d[0]), "+f"(d[1]), "+f"(d[2]), "+f"(d[3])
        : "r"(a[0]), "r"(a[1]), "r"(a[2]), "r"(a[3]), "r"(b[0]), "r"(b[1]));
}
__device__ __forceinline__ void mma16816_b(float* d, const u32* a, u32 b0, u32 b1) {
    u32 b[2] = {b0, b1};
    mma16816(d, a, b);
}

// ldmatrix x4: four m8n8 b16 tiles in one op.
__device__ __forceinline__ void ldsmA(u32* fr, u32 addr) {
    asm volatile("ldmatrix.sync.aligned.m8n8.x4.shared.b16 {%0,%1,%2,%3}, [%4];"
        : "=r"(fr[0]), "=r"(fr[1]), "=r"(fr[2]), "=r"(fr[3]) : "r"(addr));
}

// ---- prep kernel (verified): 16384 jobs, one uint4 each ----
__global__ void prep_weights(const float* __restrict__ wq, const float* __restrict__ wk,
                             const float* __restrict__ wv, const float* __restrict__ wo) {
    int i = blockIdx.x * blockDim.x + threadIdx.x;
    if (i < 12288) {  // qkv: i = (j*8+kt)*32 + lane
        int lane = i & 31, kt = (i >> 5) & 7, j = i >> 8;
        int tig = lane & 3, gg = lane >> 2;
        int m = j >> 4, h = (j >> 2) & 3, dt = j & 3;
        const float* w = ((m == 0) ? wq : ((m == 1) ? wk : wv)) + h * 4096;
        int d = dt * 8 + gg;
        int e0 = kt * 16 + 2 * tig;
        u32 h0, l0, h1, l1;
        split_pair(w[e0 * 32 + d], w[(e0 + 1) * 32 + d], h0, l0);
        split_pair(w[(e0 + 8) * 32 + d], w[(e0 + 9) * 32 + d], h1, l1);
        g_wqkv_i[i] = make_uint4(h0, h1, l0, l1);
    } else if (i < 16384) {  // wo
        int k = i - 12288;
        int lane = k & 31, kt = (k >> 5) & 7, nt = k >> 8;
        int tig = lane & 3, gg = lane >> 2;
        int o = nt * 8 + gg;
        int hd0 = kt * 16 + 2 * tig;
        u32 h0, l0, h1, l1;
        split_pair(wo[hd0 * 128 + o], wo[(hd0 + 1) * 128 + o], h0, l0);
        split_pair(wo[(hd0 + 8) * 128 + o], wo[(hd0 + 9) * 128 + o], h1, l1);
        g_wo_i[k] = make_uint4(h0, h1, l0, l1);
    }
}

// ---- smem layout (bytes), 2 batches per CTA ----
// X/HD per batch bb: XH at bb*17408, XL at bb*17408+8704          (34816)
// Q per batch: QH = OFF_Q + bb*20480, QL = QH + 10240             (40960)
// K (reused as A): OFF_K + bb*20480 (+10240 lo)                   (40960)
// VT: OFF_VT + bb*20480 (+10240 lo)                               (40960)
#define OFF_Q 34816
#define OFF_K 75776
#define OFF_VT 116736
#define SMEM_BYTES 157696

extern __shared__ char smem_raw[];

__global__ __launch_bounds__(512, 1)
void attn_mma_kernel(const float* __restrict__ x, float* __restrict__ out) {
    const int tid = threadIdx.x;
    const int lane = tid & 31, w = tid >> 5;       // 16 warps
    const int g = lane >> 2, tig = lane & 3;
    const long long b0 = (long long)blockIdx.x * 2;
    const u32 sb = smem_u32(smem_raw);

    // ldmatrix per-lane address offsets
    const int q4 = lane >> 3;
    const int lrow = (lane & 7) + ((q4 & 1) << 3);
    const int lcol = (q4 & 2) << 2;  // 0 or 8 halfs

    // ---- prefetch ph1 kt=0 weight fragments (overlaps x DRAM latency) ----
    uint4 wpf[3];
#pragma unroll
    for (int nj = 0; nj < 3; nj++)
        wpf[nj] = __ldg(g_wqkv_i + ((w * 3 + nj) * 8 + 0) * 32 + lane);

    // ---- load x for both batches (warps 0-7: batch 0, warps 8-15: batch 1) ----
    {
        const int bb = w >> 3, t2 = tid & 255;
        __half* XH = (__half*)(smem_raw + bb * 17408);
        __half* XL = (__half*)(smem_raw + bb * 17408 + 8704);
        const float2* xb2 = (const float2*)(x + (b0 + bb) * 4096LL);
#pragma unroll
        for (int i = 0; i < 8; i++) {
            int idx = t2 + i * 256;  // s = idx/64, e2 = idx%64
            int s = idx >> 6, e2 = idx & 63;
            float2 v = xb2[idx];
            u32 hi, lo;
            split_pair(v.x, v.y, hi, lo);
            *(u32*)&XH[s * 136 + e2 * 2] = hi;
            *(u32*)&XL[s * 136 + e2 * 2] = lo;
        }
    }
    __syncthreads();

    // ---- phase 1: QKV for BOTH batches: [64,128] @ Wqkv[128,384], 3 n-cols/warp ----
    {
        float acc[4][3][4];  // mt = bb*2 + mh
#pragma unroll
        for (int mt = 0; mt < 4; mt++)
#pragma unroll
            for (int nj = 0; nj < 3; nj++)
#pragma unroll
                for (int c = 0; c < 4; c++) acc[mt][nj][c] = 0.0f;

#pragma unroll
        for (int kt = 0; kt < 8; kt++) {
            uint4 bq[3];
#pragma unroll
            for (int nj = 0; nj < 3; nj++)
                bq[nj] = (kt == 0) ? wpf[nj]
                                   : __ldg(g_wqkv_i + ((w * 3 + nj) * 8 + kt) * 32 + lane);
#pragma unroll
            for (int bb = 0; bb < 2; bb++) {
                u32 ah[2][4], al[2][4];
#pragma unroll
                for (int mh = 0; mh < 2; mh++) {
                    u32 a0 = sb + bb * 17408 + ((mh * 16 + lrow) * 136 + kt * 16 + lcol) * 2;
                    ldsmA(ah[mh], a0);
                    ldsmA(al[mh], a0 + 8704);
                }
#pragma unroll
                for (int nj = 0; nj < 3; nj++) {
                    u32 bh[2] = {bq[nj].x, bq[nj].y}, bl[2] = {bq[nj].z, bq[nj].w};
#pragma unroll
                    for (int mh = 0; mh < 2; mh++) {
                        float* a = acc[bb * 2 + mh][nj];
                        mma16816(a, ah[mh], bh);
                        mma16816(a, ah[mh], bl);
                        mma16816(a, al[mh], bh);
                    }
                }
            }
        }
        // epilogue: split + scatter to per-batch Q/K/VT
#pragma unroll
        for (int nj = 0; nj < 3; nj++) {
            int j = w * 3 + nj;
            int m = j >> 4, h = (j >> 2) & 3, dt = j & 3;
#pragma unroll
            for (int mt = 0; mt < 4; mt++) {
                int bb = mt >> 1;
                __half* QH  = (__half*)(smem_raw + OFF_Q  + bb * 20480);
                __half* QL  = (__half*)(smem_raw + OFF_Q  + bb * 20480 + 10240);
                __half* KH  = (__half*)(smem_raw + OFF_K  + bb * 20480);
                __half* KL  = (__half*)(smem_raw + OFF_K  + bb * 20480 + 10240);
                __half* VTH = (__half*)(smem_raw + OFF_VT + bb * 20480);
                __half* VTL = (__half*)(smem_raw + OFF_VT + bb * 20480 + 10240);
                float c0 = acc[mt][nj][0], c1 = acc[mt][nj][1];
                float c2 = acc[mt][nj][2], c3 = acc[mt][nj][3];
                int r0 = (mt & 1) * 16 + g, r1 = r0 + 8;
                int d0 = dt * 8 + 2 * tig;
                if (m == 0) {
                    c0 *= SCALE_; c1 *= SCALE_; c2 *= SCALE_; c3 *= SCALE_;
                    u32 hi, lo;
                    split_pair(c0, c1, hi, lo);
                    *(u32*)&QH[h * 1280 + r0 * 40 + d0] = hi;
                    *(u32*)&QL[h * 1280 + r0 * 40 + d0] = lo;
                    split_pair(c2, c3, hi, lo);
                    *(u32*)&QH[h * 1280 + r1 * 40 + d0] = hi;
                    *(u32*)&QL[h * 1280 + r1 * 40 + d0] = lo;
                } else if (m == 1) {
                    u32 hi, lo;
                    split_pair(c0, c1, hi, lo);
                    *(u32*)&KH[h * 1280 + r0 * 40 + d0] = hi;
                    *(u32*)&KL[h * 1280 + r0 * 40 + d0] = lo;
                    split_pair(c2, c3, hi, lo);
                    *(u32*)&KH[h * 1280 + r1 * 40 + d0] = hi;
                    *(u32*)&KL[h * 1280 + r1 * 40 + d0] = lo;
                } else {
                    split_one(c0, &VTH[h * 1280 + d0 * 40 + r0], &VTL[h * 1280 + d0 * 40 + r0]);
                    split_one(c1, &VTH[h * 1280 + (d0 + 1) * 40 + r0], &VTL[h * 1280 + (d0 + 1) * 40 + r0]);
                    split_one(c2, &VTH[h * 1280 + d0 * 40 + r1], &VTL[h * 1280 + d0 * 40 + r1]);
                    split_one(c3, &VTH[h * 1280 + (d0 + 1) * 40 + r1], &VTL[h * 1280 + (d0 + 1) * 40 + r1]);
                }
            }
        }
    }
    __syncthreads();

    // ---- prefetch ph5 Wo fragments for kt=0,1 ----
    uint4 wo_pf[4];
    {
        int wl = w & 7;
#pragma unroll
        for (int i = 0; i < 4; i++) {
            int kt = i >> 1, ntl = i & 1;
            wo_pf[i] = __ldg(g_wo_i + ((wl * 2 + ntl) * 8 + kt) * 32 + lane);
        }
    }

    // ---- fused phases 2+3+4 (warp-local): warp w -> (bb, h, mt) ----
    {
        int bb = w >> 3, h = (w >> 1) & 3, mt = w & 1;
        const u32 qbase  = sb + OFF_Q  + bb * 20480;
        const u32 kbase  = sb + OFF_K  + bb * 20480;
        const u32 vbase  = sb + OFF_VT + bb * 20480;
        __half* HDH = (__half*)(smem_raw + bb * 17408);
        __half* HDL = (__half*)(smem_raw + bb * 17408 + 8704);

        float acc[4][4];
#pragma unroll
        for (int nt = 0; nt < 4; nt++)
#pragma unroll
            for (int c = 0; c < 4; c++) acc[nt][c] = 0.0f;

        // phase 2: scores = Q @ K^T
#pragma unroll
        for (int kt = 0; kt < 2; kt++) {
            u32 qh[4], ql[4];
            u32 a0 = qbase + (h * 1280 + (mt * 16 + lrow) * 40 + kt * 16 + lcol) * 2;
            ldsmA(qh, a0);
            ldsmA(ql, a0 + 10240);
#pragma unroll
            for (int ntp = 0; ntp < 2; ntp++) {
                u32 kb[4], kl[4];
                u32 ka = kbase + (h * 1280 + (ntp * 16 + lrow) * 40 + kt * 16 + lcol) * 2;
                ldsmA(kb, ka);
                ldsmA(kl, ka + 10240);
                mma16816_b(acc[2 * ntp], qh, kb[0], kb[2]);
                mma16816_b(acc[2 * ntp], qh, kl[0], kl[2]);
                mma16816_b(acc[2 * ntp], ql, kb[0], kb[2]);
                mma16816_b(acc[2 * ntp + 1], qh, kb[1], kb[3]);
                mma16816_b(acc[2 * ntp + 1], qh, kl[1], kl[3]);
                mma16816_b(acc[2 * ntp + 1], ql, kb[1], kb[3]);
            }
        }

        // phase 3: softmax in registers (quad shuffle reduction)
        float mx0 = -1e30f, mx1 = -1e30f;
#pragma unroll
        for (int nt = 0; nt < 4; nt++) {
            mx0 = fmaxf(mx0, fmaxf(acc[nt][0], acc[nt][1]));
            mx1 = fmaxf(mx1, fmaxf(acc[nt][2], acc[nt][3]));
        }
        mx0 = fmaxf(mx0, __shfl_xor_sync(0xFFFFFFFF, mx0, 1));
        mx0 = fmaxf(mx0, __shfl_xor_sync(0xFFFFFFFF, mx0, 2));
        mx1 = fmaxf(mx1, __shfl_xor_sync(0xFFFFFFFF, mx1, 1));
        mx1 = fmaxf(mx1, __shfl_xor_sync(0xFFFFFFFF, mx1, 2));
        float s0 = 0.0f, s1 = 0.0f;
#pragma unroll
        for (int nt = 0; nt < 4; nt++) {
            acc[nt][0] = __expf(acc[nt][0] - mx0); s0 += acc[nt][0];
            acc[nt][1] = __expf(acc[nt][1] - mx0); s0 += acc[nt][1];
            acc[nt][2] = __expf(acc[nt][2] - mx1); s1 += acc[nt][2];
            acc[nt][3] = __expf(acc[nt][3] - mx1); s1 += acc[nt][3];
        }
        s0 += __shfl_xor_sync(0xFFFFFFFF, s0, 1);
        s0 += __shfl_xor_sync(0xFFFFFFFF, s0, 2);
        s1 += __shfl_xor_sync(0xFFFFFFFF, s1, 1);
        s1 += __shfl_xor_sync(0xFFFFFFFF, s1, 2);
        float i0 = 1.0f / s0, i1 = 1.0f / s1;

        // normalized scores -> A-fragments (hi/lo split); D-layout == A-layout
        u32 aah[2][4], aal[2][4];
#pragma unroll
        for (int kt = 0; kt < 2; kt++) {
            split_pair(acc[2 * kt][0] * i0,     acc[2 * kt][1] * i0,     aah[kt][0], aal[kt][0]);
            split_pair(acc[2 * kt][2] * i1,     acc[2 * kt][3] * i1,     aah[kt][1], aal[kt][1]);
            split_pair(acc[2 * kt + 1][0] * i0, acc[2 * kt + 1][1] * i0, aah[kt][2], aal[kt][2]);
            split_pair(acc[2 * kt + 1][2] * i1, acc[2 * kt + 1][3] * i1, aah[kt][3], aal[kt][3]);
        }

        // phase 4: Hd = A @ V
        float hd[4][4];
#pragma unroll
        for (int nt = 0; nt < 4; nt++)
#pragma unroll
            for (int c = 0; c < 4; c++) hd[nt][c] = 0.0f;
#pragma unroll
        for (int kt = 0; kt < 2; kt++) {
#pragma unroll
            for (int ntp = 0; ntp < 2; ntp++) {
                u32 vb[4], vl[4];
                u32 va = vbase + (h * 1280 + (ntp * 16 + lrow) * 40 + kt * 16 + lcol) * 2;
                ldsmA(vb, va);
                ldsmA(vl, va + 10240);
                mma16816_b(hd[2 * ntp], aah[kt], vb[0], vb[2]);
                mma16816_b(hd[2 * ntp], aah[kt], vl[0], vl[2]);
                mma16816_b(hd[2 * ntp], aal[kt], vb[0], vb[2]);
                mma16816_b(hd[2 * ntp + 1], aah[kt], vb[1], vb[3]);
                mma16816_b(hd[2 * ntp + 1], aah[kt], vl[1], vl[3]);
                mma16816_b(hd[2 * ntp + 1], aal[kt], vb[1], vb[3]);
            }
        }
        // epilogue -> HDH/HDL [s][h*32+d]
#pragma unroll
        for (int nt = 0; nt < 4; nt++) {
            int col = h * 32 + nt * 8 + 2 * tig;
            int r0 = mt * 16 + g, r1 = r0 + 8;
            u32 hi, lo;
            split_pair(hd[nt][0], hd[nt][1], hi, lo);
            *(u32*)&HDH[r0 * 136 + col] = hi;
            *(u32*)&HDL[r0 * 136 + col] = lo;
            split_pair(hd[nt][2], hd[nt][3], hi, lo);
            *(u32*)&HDH[r1 * 136 + col] = hi;
            *(u32*)&HDL[r1 * 136 + col] = lo;
        }
    }
    __syncthreads();

    // ---- phase 5: out[bb] = Hd[bb][32,128] @ WoFlat[128,128] (warps 0-7: bb=0) ----
    {
        int bb = w >> 3, wl = w & 7;
        const u32 hbase = sb + bb * 17408;
        float acc[2][2][4];
#pragma unroll
        for (int mt = 0; mt < 2; mt++)
#pragma unroll
            for (int n = 0; n < 2; n++)
#pragma unroll
                for (int c = 0; c < 4; c++) acc[mt][n][c] = 0.0f;
#pragma unroll
        for (int kt = 0; kt < 8; kt++) {
            u32 ah[2][4], al[2][4];
#pragma unroll
            for (int mt = 0; mt < 2; mt++) {
                u32 a0 = hbase + ((mt * 16 + lrow) * 136 + kt * 16 + lcol) * 2;
                ldsmA(ah[mt], a0);
                ldsmA(al[mt], a0 + 8704);
            }
#pragma unroll
            for (int ntl = 0; ntl < 2; ntl++) {
                int nt = wl * 2 + ntl;
                uint4 bq = (kt < 2) ? wo_pf[kt * 2 + ntl]
                                    : __ldg(g_wo_i + (nt * 8 + kt) * 32 + lane);
                u32 bh[2] = {bq.x, bq.y}, bl2[2] = {bq.z, bq.w};
#pragma unroll
                for (int mt = 0; mt < 2; mt++) {
                    mma16816(acc[mt][ntl], ah[mt], bh);
                    mma16816(acc[mt][ntl], ah[mt], bl2);
                    mma16816(acc[mt][ntl], al[mt], bh);
                }
            }
        }
        float* ob = out + (b0 + bb) * 4096LL;
#pragma unroll
        for (int mt = 0; mt < 2; mt++)
#pragma unroll
            for (int ntl = 0; ntl < 2; ntl++) {
                int nt = wl * 2 + ntl;
                int r0 = mt * 16 + g, c = nt * 8 + 2 * tig;
                *(float2*)&ob[r0 * 128 + c] = make_float2(acc[mt][ntl][0], acc[mt][ntl][1]);
                *(float2*)&ob[(r0 + 8) * 128 + c] = make_float2(acc[mt][ntl][2], acc[mt][ntl][3]);
            }
    }
}

extern "C" void kernel_launch(void* const* d_in, const int* in_sizes, int n_in,
                              void* d_out, int out_size) {
    const float* x  = (const float*)d_in[0];
    const float* wq = (const float*)d_in[1];
    const float* wk = (const float*)d_in[2];
    const float* wv = (const float*)d_in[3];
    const float* wo = (const float*)d_in[4];
    float* out = (float*)d_out;

    cudaFuncSetAttribute(attn_mma_kernel,
                         cudaFuncAttributeMaxDynamicSharedMemorySize, SMEM_BYTES);

    prep_weights<<<64, 256>>>(wq, wk, wv, wo);
    attn_mma_kernel<<<NB_ / 2, 512, SMEM_BYTES>>>(x, out);
}

// round 10
// speedup vs baseline: 1.2507x; 1.2507x over previous
#include <cuda_runtime.h>
#include <cuda_fp16.h>

#define NB_ 16384
#define SCALE_ 0.17677669529663687f  // 1/sqrt(32)

typedef unsigned u32;

// ---- interleaved weight fragment buffers: uint4 = {b0_hi, b1_hi, b0_lo, b1_lo} ----
__device__ __align__(16) uint4 g_wqkv_i[48 * 8 * 32];  // 196608 B
__device__ __align__(16) uint4 g_wo_i[16 * 8 * 32];    //  65536 B

__device__ __forceinline__ void split_pair(float a, float b, u32& hi, u32& lo) {
    __half ha = __float2half_rn(a), hb = __float2half_rn(b);
    __half2 h2 = __halves2half2(ha, hb);
    hi = *(u32*)&h2;
    __half2 l2 = __floats2half2_rn(a - __half2float(ha), b - __half2float(hb));
    lo = *(u32*)&l2;
}
__device__ __forceinline__ u32 pack_hi(float a, float b) {
    __half2 h2 = __floats2half2_rn(a, b);
    return *(u32*)&h2;
}
__device__ __forceinline__ void split_one(float v, __half* ph, __half* pl) {
    __half h = __float2half_rn(v);
    *ph = h;
    *pl = __float2half_rn(v - __half2float(h));
}
__device__ __forceinline__ u32 smem_u32(const void* p) {
    u32 a;
    asm("{ .reg .u64 t; cvta.to.shared.u64 t, %1; cvt.u32.u64 %0, t; }" : "=r"(a) : "l"(p));
    return a;
}

__device__ __forceinline__ void mma16816(float* d, const u32* a, const u32* b) {
    asm volatile(
        "mma.sync.aligned.m16n8k16.row.col.f32.f16.f16.f32 "
        "{%0,%1,%2,%3}, {%4,%5,%6,%7}, {%8,%9}, {%0,%1,%2,%3};\n"
        : "+f"(d[0]), "+f"(d[1]), "+f"(d[2]), "+f"(d[3])
        : "r"(a[0]), "r"(a[1]), "r"(a[2]), "r"(a[3]), "r"(b[0]), "r"(b[1]));
}
__device__ __forceinline__ void mma16816_b(float* d, const u32* a, u32 b0, u32 b1) {
    u32 b[2] = {b0, b1};
    mma16816(d, a, b);
}

// ldmatrix x4: four m8n8 b16 tiles in one op.
__device__ __forceinline__ void ldsmA(u32* fr, u32 addr) {
    asm volatile("ldmatrix.sync.aligned.m8n8.x4.shared.b16 {%0,%1,%2,%3}, [%4];"
        : "=r"(fr[0]), "=r"(fr[1]), "=r"(fr[2]), "=r"(fr[3]) : "r"(addr));
}

// ---- prep kernel (verified): 16384 jobs, one uint4 each ----
__global__ void prep_weights(const float* __restrict__ wq, const float* __restrict__ wk,
                             const float* __restrict__ wv, const float* __restrict__ wo) {
    int i = blockIdx.x * blockDim.x + threadIdx.x;
    if (i < 12288) {  // qkv: i = (j*8+kt)*32 + lane
        int lane = i & 31, kt = (i >> 5) & 7, j = i >> 8;
        int tig = lane & 3, gg = lane >> 2;
        int m = j >> 4, h = (j >> 2) & 3, dt = j & 3;
        const float* w = ((m == 0) ? wq : ((m == 1) ? wk : wv)) + h * 4096;
        int d = dt * 8 + gg;
        int e0 = kt * 16 + 2 * tig;
        u32 h0, l0, h1, l1;
        split_pair(w[e0 * 32 + d], w[(e0 + 1) * 32 + d], h0, l0);
        split_pair(w[(e0 + 8) * 32 + d], w[(e0 + 9) * 32 + d], h1, l1);
        g_wqkv_i[i] = make_uint4(h0, h1, l0, l1);
    } else if (i < 16384) {  // wo
        int k = i - 12288;
        int lane = k & 31, kt = (k >> 5) & 7, nt = k >> 8;
        int tig = lane & 3, gg = lane >> 2;
        int o = nt * 8 + gg;
        int hd0 = kt * 16 + 2 * tig;
        u32 h0, l0, h1, l1;
        split_pair(wo[hd0 * 128 + o], wo[(hd0 + 1) * 128 + o], h0, l0);
        split_pair(wo[(hd0 + 8) * 128 + o], wo[(hd0 + 9) * 128 + o], h1, l1);
        g_wo_i[k] = make_uint4(h0, h1, l0, l1);
    }
}

// ---- smem layout (bytes) ----
#define OFF_XH 0
#define OFF_XL 8704
#define OFF_QH 17408
#define OFF_QL 27648
#define OFF_KH 37888
#define OFF_KL 48128
#define OFF_VTH 58368
#define OFF_VTL 68608
#define SMEM_BYTES 78848

extern __shared__ char smem_raw[];

__global__ __launch_bounds__(256, 2)
void attn_mma_kernel(const float* __restrict__ x, float* __restrict__ out) {
    __half* XH = (__half*)(smem_raw + OFF_XH);
    __half* XL = (__half*)(smem_raw + OFF_XL);
    __half* QH = (__half*)(smem_raw + OFF_QH);
    __half* QL = (__half*)(smem_raw + OFF_QL);
    __half* KH = (__half*)(smem_raw + OFF_KH);
    __half* KL = (__half*)(smem_raw + OFF_KL);
    __half* VTH = (__half*)(smem_raw + OFF_VTH);
    __half* VTL = (__half*)(smem_raw + OFF_VTL);
    __half* HDH = XH;  // reuse after phase 1 (fp16-hi only; no lo buffer needed)

    const int tid = threadIdx.x;
    const int lane = tid & 31, w = tid >> 5;
    const int g = lane >> 2, tig = lane & 3;
    const long long b = blockIdx.x;
    const u32 sb = smem_u32(smem_raw);

    // ldmatrix per-lane address offsets
    const int q4 = lane >> 3;
    const int lrow = (lane & 7) + ((q4 & 1) << 3);
    const int lcol = (q4 & 2) << 2;  // 0 or 8 halfs

    // ---- prefetch ph1 kt=0 weight fragments (overlaps x DRAM latency) ----
    uint4 wpf[6];
#pragma unroll
    for (int nj = 0; nj < 6; nj++)
        wpf[nj] = __ldg(g_wqkv_i + ((w * 6 + nj) * 8 + 0) * 32 + lane);

    // ---- load x, split fp16 hi/lo ----
    const float2* xb2 = (const float2*)(x + b * 4096LL);
#pragma unroll
    for (int i = 0; i < 8; i++) {
        int idx = tid + i * 256;  // s = idx/64, e2 = idx%64
        int s = idx >> 6, e2 = idx & 63;
        float2 v = xb2[idx];
        u32 hi, lo;
        split_pair(v.x, v.y, hi, lo);
        *(u32*)&XH[s * 136 + e2 * 2] = hi;
        *(u32*)&XL[s * 136 + e2 * 2] = lo;
    }
    __syncthreads();

    // ---- phase 1: QKV = X[32,128] @ Wqkv[128,384]  (3-MMA split: pre-softmax, keep full) ----
    {
        float acc[2][6][4];
#pragma unroll
        for (int mt = 0; mt < 2; mt++)
#pragma unroll
            for (int nj = 0; nj < 6; nj++)
#pragma unroll
                for (int c = 0; c < 4; c++) acc[mt][nj][c] = 0.0f;

#pragma unroll
        for (int kt = 0; kt < 8; kt++) {
            u32 ah[2][4], al[2][4];
#pragma unroll
            for (int mt = 0; mt < 2; mt++) {
                u32 a0 = sb + OFF_XH + ((mt * 16 + lrow) * 136 + kt * 16 + lcol) * 2;
                ldsmA(ah[mt], a0);
                ldsmA(al[mt], a0 + (OFF_XL - OFF_XH));
            }
#pragma unroll
            for (int nj = 0; nj < 6; nj++) {
                int j = w * 6 + nj;
                uint4 bq = (kt == 0) ? wpf[nj]
                                     : __ldg(g_wqkv_i + (j * 8 + kt) * 32 + lane);
                u32 bh[2] = {bq.x, bq.y}, bl[2] = {bq.z, bq.w};
#pragma unroll
                for (int mt = 0; mt < 2; mt++) {
                    mma16816(acc[mt][nj], ah[mt], bh);
                    mma16816(acc[mt][nj], ah[mt], bl);
                    mma16816(acc[mt][nj], al[mt], bh);
                }
            }
        }
        // epilogue: split + scatter to Q/K/VT
#pragma unroll
        for (int nj = 0; nj < 6; nj++) {
            int j = w * 6 + nj;
            int m = j >> 4, h = (j >> 2) & 3, dt = j & 3;
#pragma unroll
            for (int mt = 0; mt < 2; mt++) {
                float c0 = acc[mt][nj][0], c1 = acc[mt][nj][1];
                float c2 = acc[mt][nj][2], c3 = acc[mt][nj][3];
                int r0 = mt * 16 + g, r1 = r0 + 8;
                int d0 = dt * 8 + 2 * tig;
                if (m == 0) {
                    c0 *= SCALE_; c1 *= SCALE_; c2 *= SCALE_; c3 *= SCALE_;
                    u32 hi, lo;
                    split_pair(c0, c1, hi, lo);
                    *(u32*)&QH[h * 1280 + r0 * 40 + d0] = hi;
                    *(u32*)&QL[h * 1280 + r0 * 40 + d0] = lo;
                    split_pair(c2, c3, hi, lo);
                    *(u32*)&QH[h * 1280 + r1 * 40 + d0] = hi;
                    *(u32*)&QL[h * 1280 + r1 * 40 + d0] = lo;
                } else if (m == 1) {
                    u32 hi, lo;
                    split_pair(c0, c1, hi, lo);
                    *(u32*)&KH[h * 1280 + r0 * 40 + d0] = hi;
                    *(u32*)&KL[h * 1280 + r0 * 40 + d0] = lo;
                    split_pair(c2, c3, hi, lo);
                    *(u32*)&KH[h * 1280 + r1 * 40 + d0] = hi;
                    *(u32*)&KL[h * 1280 + r1 * 40 + d0] = lo;
                } else {
                    split_one(c0, &VTH[h * 1280 + d0 * 40 + r0], &VTL[h * 1280 + d0 * 40 + r0]);
                    split_one(c1, &VTH[h * 1280 + (d0 + 1) * 40 + r0], &VTL[h * 1280 + (d0 + 1) * 40 + r0]);
                    split_one(c2, &VTH[h * 1280 + d0 * 40 + r1], &VTL[h * 1280 + d0 * 40 + r1]);
                    split_one(c3, &VTH[h * 1280 + (d0 + 1) * 40 + r1], &VTL[h * 1280 + (d0 + 1) * 40 + r1]);
                }
            }
        }
    }
    __syncthreads();

    // ---- prefetch ph5 Wo fragments for kt=0,1 ----
    uint4 wo_pf[4];
#pragma unroll
    for (int i = 0; i < 4; i++) {
        int kt = i >> 1, ntl = i & 1;
        wo_pf[i] = __ldg(g_wo_i + ((w * 2 + ntl) * 8 + kt) * 32 + lane);
    }

    // ---- fused phases 2+3+4 (register-resident, warp-local) ----
    {
        int h = w >> 1, mt = w & 1;
        float acc[4][4];
#pragma unroll
        for (int nt = 0; nt < 4; nt++)
#pragma unroll
            for (int c = 0; c < 4; c++) acc[nt][c] = 0.0f;

        // phase 2: scores = Q @ K^T (3-MMA: pre-softmax precision critical)
#pragma unroll
        for (int kt = 0; kt < 2; kt++) {
            u32 qh[4], ql[4];
            u32 a0 = sb + OFF_QH + (h * 1280 + (mt * 16 + lrow) * 40 + kt * 16 + lcol) * 2;
            ldsmA(qh, a0);
            ldsmA(ql, a0 + (OFF_QL - OFF_QH));
#pragma unroll
            for (int ntp = 0; ntp < 2; ntp++) {
                u32 kb[4], kl[4];
                u32 ka = sb + OFF_KH + (h * 1280 + (ntp * 16 + lrow) * 40 + kt * 16 + lcol) * 2;
                ldsmA(kb, ka);
                ldsmA(kl, ka + (OFF_KL - OFF_KH));
                mma16816_b(acc[2 * ntp], qh, kb[0], kb[2]);
                mma16816_b(acc[2 * ntp], qh, kl[0], kl[2]);
                mma16816_b(acc[2 * ntp], ql, kb[0], kb[2]);
                mma16816_b(acc[2 * ntp + 1], qh, kb[1], kb[3]);
                mma16816_b(acc[2 * ntp + 1], qh, kl[1], kl[3]);
                mma16816_b(acc[2 * ntp + 1], ql, kb[1], kb[3]);
            }
        }

        // phase 3: softmax in registers (quad shuffle reduction)
        float mx0 = -1e30f, mx1 = -1e30f;
#pragma unroll
        for (int nt = 0; nt < 4; nt++) {
            mx0 = fmaxf(mx0, fmaxf(acc[nt][0], acc[nt][1]));
            mx1 = fmaxf(mx1, fmaxf(acc[nt][2], acc[nt][3]));
        }
        mx0 = fmaxf(mx0, __shfl_xor_sync(0xFFFFFFFF, mx0, 1));
        mx0 = fmaxf(mx0, __shfl_xor_sync(0xFFFFFFFF, mx0, 2));
        mx1 = fmaxf(mx1, __shfl_xor_sync(0xFFFFFFFF, mx1, 1));
        mx1 = fmaxf(mx1, __shfl_xor_sync(0xFFFFFFFF, mx1, 2));
        float s0 = 0.0f, s1 = 0.0f;
#pragma unroll
        for (int nt = 0; nt < 4; nt++) {
            acc[nt][0] = __expf(acc[nt][0] - mx0); s0 += acc[nt][0];
            acc[nt][1] = __expf(acc[nt][1] - mx0); s0 += acc[nt][1];
            acc[nt][2] = __expf(acc[nt][2] - mx1); s1 += acc[nt][2];
            acc[nt][3] = __expf(acc[nt][3] - mx1); s1 += acc[nt][3];
        }
        s0 += __shfl_xor_sync(0xFFFFFFFF, s0, 1);
        s0 += __shfl_xor_sync(0xFFFFFFFF, s0, 2);
        s1 += __shfl_xor_sync(0xFFFFFFFF, s1, 1);
        s1 += __shfl_xor_sync(0xFFFFFFFF, s1, 2);
        float i0 = 1.0f / s0, i1 = 1.0f / s1;

        // normalized scores -> A-fragments, fp16-hi ONLY (post-softmax: lo term dropped)
        u32 aah[2][4];
#pragma unroll
        for (int kt = 0; kt < 2; kt++) {
            aah[kt][0] = pack_hi(acc[2 * kt][0] * i0,     acc[2 * kt][1] * i0);
            aah[kt][1] = pack_hi(acc[2 * kt][2] * i1,     acc[2 * kt][3] * i1);
            aah[kt][2] = pack_hi(acc[2 * kt + 1][0] * i0, acc[2 * kt + 1][1] * i0);
            aah[kt][3] = pack_hi(acc[2 * kt + 1][2] * i1, acc[2 * kt + 1][3] * i1);
        }

        // phase 4: Hd = A @ V  (2-MMA: A-hi x V-hi + A-hi x V-lo)
        float hd[4][4];
#pragma unroll
        for (int nt = 0; nt < 4; nt++)
#pragma unroll
            for (int c = 0; c < 4; c++) hd[nt][c] = 0.0f;
#pragma unroll
        for (int kt = 0; kt < 2; kt++) {
#pragma unroll
            for (int ntp = 0; ntp < 2; ntp++) {
                u32 vb[4], vl[4];
                u32 va = sb + OFF_VTH + (h * 1280 + (ntp * 16 + lrow) * 40 + kt * 16 + lcol) * 2;
                ldsmA(vb, va);
                ldsmA(vl, va + (OFF_VTL - OFF_VTH));
                mma16816_b(hd[2 * ntp], aah[kt], vb[0], vb[2]);
                mma16816_b(hd[2 * ntp], aah[kt], vl[0], vl[2]);
                mma16816_b(hd[2 * ntp + 1], aah[kt], vb[1], vb[3]);
                mma16816_b(hd[2 * ntp + 1], aah[kt], vl[1], vl[3]);
            }
        }
        // epilogue -> HDH only (fp16-hi; Hd-lo dropped for ph5)
#pragma unroll
        for (int nt = 0; nt < 4; nt++) {
            int col = h * 32 + nt * 8 + 2 * tig;
            int r0 = mt * 16 + g, r1 = r0 + 8;
            *(u32*)&HDH[r0 * 136 + col] = pack_hi(hd[nt][0], hd[nt][1]);
            *(u32*)&HDH[r1 * 136 + col] = pack_hi(hd[nt][2], hd[nt][3]);
        }
    }
    __syncthreads();

    // ---- phase 5: out = Hd[32,128] @ WoFlat[128,128]  (2-MMA: Hd-hi x Wo-hi + Hd-hi x Wo-lo) ----
    {
        float acc[2][2][4];
#pragma unroll
        for (int mt = 0; mt < 2; mt++)
#pragma unroll
            for (int n = 0; n < 2; n++)
#pragma unroll
                for (int c = 0; c < 4; c++) acc[mt][n][c] = 0.0f;
#pragma unroll
        for (int kt = 0; kt < 8; kt++) {
            u32 ah[2][4];
#pragma unroll
            for (int mt = 0; mt < 2; mt++) {
                u32 a0 = sb + OFF_XH + ((mt * 16 + lrow) * 136 + kt * 16 + lcol) * 2;
                ldsmA(ah[mt], a0);
            }
#pragma unroll
            for (int ntl = 0; ntl < 2; ntl++) {
                int nt = w * 2 + ntl;
                uint4 bq = (kt < 2) ? wo_pf[kt * 2 + ntl]
                                    : __ldg(g_wo_i + (nt * 8 + kt) * 32 + lane);
                u32 bh[2] = {bq.x, bq.y}, bl2[2] = {bq.z, bq.w};
#pragma unroll
                for (int mt = 0; mt < 2; mt++) {
                    mma16816(acc[mt][ntl], ah[mt], bh);
                    mma16816(acc[mt][ntl], ah[mt], bl2);
                }
            }
        }
        float* ob = out + b * 4096LL;
#pragma unroll
        for (int mt = 0; mt < 2; mt++)
#pragma unroll
            for (int ntl = 0; ntl < 2; ntl++) {
                int nt = w * 2 + ntl;
                int r0 = mt * 16 + g, c = nt * 8 + 2 * tig;
                *(float2*)&ob[r0 * 128 + c] = make_float2(acc[mt][ntl][0], acc[mt][ntl][1]);
                *(float2*)&ob[(r0 + 8) * 128 + c] = make_float2(acc[mt][ntl][2], acc[mt][ntl][3]);
            }
    }
}

extern "C" void kernel_launch(void* const* d_in, const int* in_sizes, int n_in,
                              void* d_out, int out_size) {
    const float* x  = (const float*)d_in[0];
    const float* wq = (const float*)d_in[1];
    const float* wk = (const float*)d_in[2];
    const float* wv = (const float*)d_in[3];
    const float* wo = (const float*)d_in[4];
    float* out = (float*)d_out;

    cudaFuncSetAttribute(attn_mma_kernel,
                         cudaFuncAttributeMaxDynamicSharedMemorySize, SMEM_BYTES);

    prep_weights<<<64, 256>>>(wq, wk, wv, wo);
    attn_mma_kernel<<<NB_, 256, SMEM_BYTES>>>(x, out);
}

// round 11
// speedup vs baseline: 1.4606x; 1.1678x over previous
#include <cuda_runtime.h>
#include <cuda_fp16.h>

#define NB_ 16384
#define SCALE_ 0.17677669529663687f  // 1/sqrt(32)

typedef unsigned u32;

// ---- interleaved weight fragment buffers: uint4 = {b0_hi, b1_hi, b0_lo, b1_lo} ----
__device__ __align__(16) uint4 g_wqkv_i[48 * 8 * 32];  // 196608 B
__device__ __align__(16) uint4 g_wo_i[16 * 8 * 32];    //  65536 B

__device__ __forceinline__ void split_pair(float a, float b, u32& hi, u32& lo) {
    __half ha = __float2half_rn(a), hb = __float2half_rn(b);
    __half2 h2 = __halves2half2(ha, hb);
    hi = *(u32*)&h2;
    __half2 l2 = __floats2half2_rn(a - __half2float(ha), b - __half2float(hb));
    lo = *(u32*)&l2;
}
__device__ __forceinline__ u32 pack_hi(float a, float b) {
    __half2 h2 = __floats2half2_rn(a, b);
    return *(u32*)&h2;
}
__device__ __forceinline__ u32 smem_u32(const void* p) {
    u32 a;
    asm("{ .reg .u64 t; cvta.to.shared.u64 t, %1; cvt.u32.u64 %0, t; }" : "=r"(a) : "l"(p));
    return a;
}

__device__ __forceinline__ void mma16816(float* d, const u32* a, const u32* b) {
    asm volatile(
        "mma.sync.aligned.m16n8k16.row.col.f32.f16.f16.f32 "
        "{%0,%1,%2,%3}, {%4,%5,%6,%7}, {%8,%9}, {%0,%1,%2,%3};\n"
        : "+f"(d[0]), "+f"(d[1]), "+f"(d[2]), "+f"(d[3])
        : "r"(a[0]), "r"(a[1]), "r"(a[2]), "r"(a[3]), "r"(b[0]), "r"(b[1]));
}
__device__ __forceinline__ void mma16816_b(float* d, const u32* a, u32 b0, u32 b1) {
    u32 b[2] = {b0, b1};
    mma16816(d, a, b);
}

// ldmatrix x4: four m8n8 b16 tiles in one op.
__device__ __forceinline__ void ldsmA(u32* fr, u32 addr) {
    asm volatile("ldmatrix.sync.aligned.m8n8.x4.shared.b16 {%0,%1,%2,%3}, [%4];"
        : "=r"(fr[0]), "=r"(fr[1]), "=r"(fr[2]), "=r"(fr[3]) : "r"(addr));
}

// ---- prep kernel (verified): 16384 jobs, one uint4 each ----
__global__ void prep_weights(const float* __restrict__ wq, const float* __restrict__ wk,
                             const float* __restrict__ wv, const float* __restrict__ wo) {
    int i = blockIdx.x * blockDim.x + threadIdx.x;
    if (i < 12288) {  // qkv: i = (j*8+kt)*32 + lane
        int lane = i & 31, kt = (i >> 5) & 7, j = i >> 8;
        int tig = lane & 3, gg = lane >> 2;
        int m = j >> 4, h = (j >> 2) & 3, dt = j & 3;
        const float* w = ((m == 0) ? wq : ((m == 1) ? wk : wv)) + h * 4096;
        int d = dt * 8 + gg;
        int e0 = kt * 16 + 2 * tig;
        u32 h0, l0, h1, l1;
        split_pair(w[e0 * 32 + d], w[(e0 + 1) * 32 + d], h0, l0);
        split_pair(w[(e0 + 8) * 32 + d], w[(e0 + 9) * 32 + d], h1, l1);
        g_wqkv_i[i] = make_uint4(h0, h1, l0, l1);
    } else if (i < 16384) {  // wo
        int k = i - 12288;
        int lane = k & 31, kt = (k >> 5) & 7, nt = k >> 8;
        int tig = lane & 3, gg = lane >> 2;
        int o = nt * 8 + gg;
        int hd0 = kt * 16 + 2 * tig;
        u32 h0, l0, h1, l1;
        split_pair(wo[hd0 * 128 + o], wo[(hd0 + 1) * 128 + o], h0, l0);
        split_pair(wo[(hd0 + 8) * 128 + o], wo[(hd0 + 9) * 128 + o], h1, l1);
        g_wo_i[k] = make_uint4(h0, h1, l0, l1);
    }
}

// ---- smem layout (bytes); VT-lo eliminated ----
#define OFF_XH 0
#define OFF_XL 8704
#define OFF_QH 17408
#define OFF_QL 27648
#define OFF_KH 37888
#define OFF_KL 48128
#define OFF_VTH 58368
#define SMEM_BYTES 68608

extern __shared__ char smem_raw[];

__global__ __launch_bounds__(256, 2)
void attn_mma_kernel(const float* __restrict__ x, float* __restrict__ out) {
    __half* XH = (__half*)(smem_raw + OFF_XH);
    __half* XL = (__half*)(smem_raw + OFF_XL);
    __half* QH = (__half*)(smem_raw + OFF_QH);
    __half* QL = (__half*)(smem_raw + OFF_QL);
    __half* KH = (__half*)(smem_raw + OFF_KH);
    __half* KL = (__half*)(smem_raw + OFF_KL);
    __half* VTH = (__half*)(smem_raw + OFF_VTH);
    __half* HDH = XH;  // reuse after phase 1 (fp16-hi only)

    const int tid = threadIdx.x;
    const int lane = tid & 31, w = tid >> 5;
    const int g = lane >> 2, tig = lane & 3;
    const long long b = blockIdx.x;
    const u32 sb = smem_u32(smem_raw);

    // ldmatrix per-lane address offsets
    const int q4 = lane >> 3;
    const int lrow = (lane & 7) + ((q4 & 1) << 3);
    const int lcol = (q4 & 2) << 2;  // 0 or 8 halfs

    // ---- prefetch ph1 kt=0 weight fragments (strided j = nj*8 + w) ----
    uint4 wpf[6];
#pragma unroll
    for (int nj = 0; nj < 6; nj++)
        wpf[nj] = __ldg(g_wqkv_i + ((nj * 8 + w) * 8 + 0) * 32 + lane);

    // ---- load x, split fp16 hi/lo ----
    const float2* xb2 = (const float2*)(x + b * 4096LL);
#pragma unroll
    for (int i = 0; i < 8; i++) {
        int idx = tid + i * 256;  // s = idx/64, e2 = idx%64
        int s = idx >> 6, e2 = idx & 63;
        float2 v = xb2[idx];
        u32 hi, lo;
        split_pair(v.x, v.y, hi, lo);
        *(u32*)&XH[s * 136 + e2 * 2] = hi;
        *(u32*)&XL[s * 136 + e2 * 2] = lo;
    }
    __syncthreads();

    // ---- phase 1: QKV = X[32,128] @ Wqkv[128,384] ----
    // j = nj*8 + w  =>  m = nj>>1 (compile-time): nj 0,1 = Q; 2,3 = K; 4,5 = V.
    // Q/K: 3-MMA (pre-softmax precision). V: 2-MMA (post-softmax path, X-lo term dropped).
    {
        float acc[2][6][4];
#pragma unroll
        for (int mt = 0; mt < 2; mt++)
#pragma unroll
            for (int nj = 0; nj < 6; nj++)
#pragma unroll
                for (int c = 0; c < 4; c++) acc[mt][nj][c] = 0.0f;

#pragma unroll
        for (int kt = 0; kt < 8; kt++) {
            u32 ah[2][4], al[2][4];
#pragma unroll
            for (int mt = 0; mt < 2; mt++) {
                u32 a0 = sb + OFF_XH + ((mt * 16 + lrow) * 136 + kt * 16 + lcol) * 2;
                ldsmA(ah[mt], a0);
                ldsmA(al[mt], a0 + (OFF_XL - OFF_XH));
            }
#pragma unroll
            for (int nj = 0; nj < 6; nj++) {
                uint4 bq = (kt == 0) ? wpf[nj]
                                     : __ldg(g_wqkv_i + ((nj * 8 + w) * 8 + kt) * 32 + lane);
                u32 bh[2] = {bq.x, bq.y}, bl[2] = {bq.z, bq.w};
#pragma unroll
                for (int mt = 0; mt < 2; mt++) {
                    mma16816(acc[mt][nj], ah[mt], bh);
                    mma16816(acc[mt][nj], ah[mt], bl);
                    if (nj < 4) mma16816(acc[mt][nj], al[mt], bh);  // compile-time predicate
                }
            }
        }
        // epilogue: split + scatter to Q/K/VT
#pragma unroll
        for (int nj = 0; nj < 6; nj++) {
            int j = nj * 8 + w;
            int h = (j >> 2) & 3, dt = j & 3;
#pragma unroll
            for (int mt = 0; mt < 2; mt++) {
                float c0 = acc[mt][nj][0], c1 = acc[mt][nj][1];
                float c2 = acc[mt][nj][2], c3 = acc[mt][nj][3];
                int r0 = mt * 16 + g, r1 = r0 + 8;
                int d0 = dt * 8 + 2 * tig;
                if (nj < 2) {  // Q
                    c0 *= SCALE_; c1 *= SCALE_; c2 *= SCALE_; c3 *= SCALE_;
                    u32 hi, lo;
                    split_pair(c0, c1, hi, lo);
                    *(u32*)&QH[h * 1280 + r0 * 40 + d0] = hi;
                    *(u32*)&QL[h * 1280 + r0 * 40 + d0] = lo;
                    split_pair(c2, c3, hi, lo);
                    *(u32*)&QH[h * 1280 + r1 * 40 + d0] = hi;
                    *(u32*)&QL[h * 1280 + r1 * 40 + d0] = lo;
                } else if (nj < 4) {  // K
                    u32 hi, lo;
                    split_pair(c0, c1, hi, lo);
                    *(u32*)&KH[h * 1280 + r0 * 40 + d0] = hi;
                    *(u32*)&KL[h * 1280 + r0 * 40 + d0] = lo;
                    split_pair(c2, c3, hi, lo);
                    *(u32*)&KH[h * 1280 + r1 * 40 + d0] = hi;
                    *(u32*)&KL[h * 1280 + r1 * 40 + d0] = lo;
                } else {  // V (fp16-hi only), transposed: VT[h][d][t]
                    VTH[h * 1280 + d0 * 40 + r0]       = __float2half_rn(c0);
                    VTH[h * 1280 + (d0 + 1) * 40 + r0] = __float2half_rn(c1);
                    VTH[h * 1280 + d0 * 40 + r1]       = __float2half_rn(c2);
                    VTH[h * 1280 + (d0 + 1) * 40 + r1] = __float2half_rn(c3);
                }
            }
        }
    }
    __syncthreads();

    // ---- prefetch ph5 Wo fragments for kt=0,1 (only hi halves used) ----
    uint4 wo_pf[4];
#pragma unroll
    for (int i = 0; i < 4; i++) {
        int kt = i >> 1, ntl = i & 1;
        wo_pf[i] = __ldg(g_wo_i + ((w * 2 + ntl) * 8 + kt) * 32 + lane);
    }

    // ---- fused phases 2+3+4 (register-resident, warp-local) ----
    {
        int h = w >> 1, mt = w & 1;
        float acc[4][4];
#pragma unroll
        for (int nt = 0; nt < 4; nt++)
#pragma unroll
            for (int c = 0; c < 4; c++) acc[nt][c] = 0.0f;

        // phase 2: scores = Q @ K^T (3-MMA: pre-softmax precision critical)
#pragma unroll
        for (int kt = 0; kt < 2; kt++) {
            u32 qh[4], ql[4];
            u32 a0 = sb + OFF_QH + (h * 1280 + (mt * 16 + lrow) * 40 + kt * 16 + lcol) * 2;
            ldsmA(qh, a0);
            ldsmA(ql, a0 + (OFF_QL - OFF_QH));
#pragma unroll
            for (int ntp = 0; ntp < 2; ntp++) {
                u32 kb[4], kl[4];
                u32 ka = sb + OFF_KH + (h * 1280 + (ntp * 16 + lrow) * 40 + kt * 16 + lcol) * 2;
                ldsmA(kb, ka);
                ldsmA(kl, ka + (OFF_KL - OFF_KH));
                mma16816_b(acc[2 * ntp], qh, kb[0], kb[2]);
                mma16816_b(acc[2 * ntp], qh, kl[0], kl[2]);
                mma16816_b(acc[2 * ntp], ql, kb[0], kb[2]);
                mma16816_b(acc[2 * ntp + 1], qh, kb[1], kb[3]);
                mma16816_b(acc[2 * ntp + 1], qh, kl[1], kl[3]);
                mma16816_b(acc[2 * ntp + 1], ql, kb[1], kb[3]);
            }
        }

        // phase 3: softmax in registers (quad shuffle reduction)
        float mx0 = -1e30f, mx1 = -1e30f;
#pragma unroll
        for (int nt = 0; nt < 4; nt++) {
            mx0 = fmaxf(mx0, fmaxf(acc[nt][0], acc[nt][1]));
            mx1 = fmaxf(mx1, fmaxf(acc[nt][2], acc[nt][3]));
        }
        mx0 = fmaxf(mx0, __shfl_xor_sync(0xFFFFFFFF, mx0, 1));
        mx0 = fmaxf(mx0, __shfl_xor_sync(0xFFFFFFFF, mx0, 2));
        mx1 = fmaxf(mx1, __shfl_xor_sync(0xFFFFFFFF, mx1, 1));
        mx1 = fmaxf(mx1, __shfl_xor_sync(0xFFFFFFFF, mx1, 2));
        float s0 = 0.0f, s1 = 0.0f;
#pragma unroll
        for (int nt = 0; nt < 4; nt++) {
            acc[nt][0] = __expf(acc[nt][0] - mx0); s0 += acc[nt][0];
            acc[nt][1] = __expf(acc[nt][1] - mx0); s0 += acc[nt][1];
            acc[nt][2] = __expf(acc[nt][2] - mx1); s1 += acc[nt][2];
            acc[nt][3] = __expf(acc[nt][3] - mx1); s1 += acc[nt][3];
        }
        s0 += __shfl_xor_sync(0xFFFFFFFF, s0, 1);
        s0 += __shfl_xor_sync(0xFFFFFFFF, s0, 2);
        s1 += __shfl_xor_sync(0xFFFFFFFF, s1, 1);
        s1 += __shfl_xor_sync(0xFFFFFFFF, s1, 2);
        float i0 = 1.0f / s0, i1 = 1.0f / s1;

        // normalized scores -> A-fragments, fp16-hi only
        u32 aah[2][4];
#pragma unroll
        for (int kt = 0; kt < 2; kt++) {
            aah[kt][0] = pack_hi(acc[2 * kt][0] * i0,     acc[2 * kt][1] * i0);
            aah[kt][1] = pack_hi(acc[2 * kt][2] * i1,     acc[2 * kt][3] * i1);
            aah[kt][2] = pack_hi(acc[2 * kt + 1][0] * i0, acc[2 * kt + 1][1] * i0);
            aah[kt][3] = pack_hi(acc[2 * kt + 1][2] * i1, acc[2 * kt + 1][3] * i1);
        }

        // phase 4: Hd = A @ V  (1-MMA per tile: A-hi x V-hi)
        float hd[4][4];
#pragma unroll
        for (int nt = 0; nt < 4; nt++)
#pragma unroll
            for (int c = 0; c < 4; c++) hd[nt][c] = 0.0f;
#pragma unroll
        for (int kt = 0; kt < 2; kt++) {
#pragma unroll
            for (int ntp = 0; ntp < 2; ntp++) {
                u32 vb[4];
                u32 va = sb + OFF_VTH + (h * 1280 + (ntp * 16 + lrow) * 40 + kt * 16 + lcol) * 2;
                ldsmA(vb, va);
                mma16816_b(hd[2 * ntp], aah[kt], vb[0], vb[2]);
                mma16816_b(hd[2 * ntp + 1], aah[kt], vb[1], vb[3]);
            }
        }
        // epilogue -> HDH only (fp16-hi)
#pragma unroll
        for (int nt = 0; nt < 4; nt++) {
            int col = h * 32 + nt * 8 + 2 * tig;
            int r0 = mt * 16 + g, r1 = r0 + 8;
            *(u32*)&HDH[r0 * 136 + col] = pack_hi(hd[nt][0], hd[nt][1]);
            *(u32*)&HDH[r1 * 136 + col] = pack_hi(hd[nt][2], hd[nt][3]);
        }
    }
    __syncthreads();

    // ---- phase 5: out = Hd[32,128] @ WoFlat[128,128]  (1-MMA: Hd-hi x Wo-hi) ----
    {
        float acc[2][2][4];
#pragma unroll
        for (int mt = 0; mt < 2; mt++)
#pragma unroll
            for (int n = 0; n < 2; n++)
#pragma unroll
                for (int c = 0; c < 4; c++) acc[mt][n][c] = 0.0f;
#pragma unroll
        for (int kt = 0; kt < 8; kt++) {
            u32 ah[2][4];
#pragma unroll
            for (int mt = 0; mt < 2; mt++) {
                u32 a0 = sb + OFF_XH + ((mt * 16 + lrow) * 136 + kt * 16 + lcol) * 2;
                ldsmA(ah[mt], a0);
            }
#pragma unroll
            for (int ntl = 0; ntl < 2; ntl++) {
                int nt = w * 2 + ntl;
                uint4 bq = (kt < 2) ? wo_pf[kt * 2 + ntl]
                                    : __ldg(g_wo_i + (nt * 8 + kt) * 32 + lane);
                u32 bh[2] = {bq.x, bq.y};
#pragma unroll
                for (int mt = 0; mt < 2; mt++)
                    mma16816(acc[mt][ntl], ah[mt], bh);
            }
        }
        float* ob = out + b * 4096LL;
#pragma unroll
        for (int mt = 0; mt < 2; mt++)
#pragma unroll
            for (int ntl = 0; ntl < 2; ntl++) {
                int nt = w * 2 + ntl;
                int r0 = mt * 16 + g, c = nt * 8 + 2 * tig;
                *(float2*)&ob[r0 * 128 + c] = make_float2(acc[mt][ntl][0], acc[mt][ntl][1]);
                *(float2*)&ob[(r0 + 8) * 128 + c] = make_float2(acc[mt][ntl][2], acc[mt][ntl][3]);
            }
    }
}

extern "C" void kernel_launch(void* const* d_in, const int* in_sizes, int n_in,
                              void* d_out, int out_size) {
    const float* x  = (const float*)d_in[0];
    const float* wq = (const float*)d_in[1];
    const float* wk = (const float*)d_in[2];
    const float* wv = (const float*)d_in[3];
    const float* wo = (const float*)d_in[4];
    float* out = (float*)d_out;

    cudaFuncSetAttribute(attn_mma_kernel,
                         cudaFuncAttributeMaxDynamicSharedMemorySize, SMEM_BYTES);

    prep_weights<<<64, 256>>>(wq, wk, wv, wo);
    attn_mma_kernel<<<NB_, 256, SMEM_BYTES>>>(x, out);
}